// round 2
// baseline (speedup 1.0000x reference)
#include <cuda_runtime.h>

// SelfAttention: O = softmax((X·Wq+bq)(X·Wk+bk)^T / 32) · (X·Wv+bv)
// B=4, N=4096, d_in=d_new=1024, all fp32.
//
// Strategy: staged fp32 register-tiled SGEMMs through __device__ scratch.
// HBM traffic (~1.8 GB) is negligible vs ~378 GFLOP of FFMA work, so each
// stage is a clean GEMM:
//   1) Q,K,V = X·W* + b*          (3x GEMM NN, M=16384 N=1024 K=1024)
//   2) S = (Q·K^T) * 1/32         (batched GEMM NT, 4x 4096x4096x1024)
//   3) rowwise softmax(S)
//   4) O = S·V                    (batched GEMM NN, 4x 4096x1024x4096)
// This round: double-buffered smem tiles (prefetch k+1 into registers while
// computing k; one __syncthreads per K-step).

#define BM 128
#define BN 128
#define BK 16
#define TM 8
#define TN 8

// Scratch (allocation-free rule: __device__ globals)
__device__ float g_Q[4l * 4096 * 1024];
__device__ float g_K[4l * 4096 * 1024];
__device__ float g_V[4l * 4096 * 1024];
__device__ float g_S[4l * 4096 * 4096];

// TRANS_B == 0: B is [K x N] row-major (NN)
// TRANS_B == 1: B is [N x K] row-major (NT, i.e. C = A * B^T)
template <int TRANS_B>
__global__ __launch_bounds__(256, 2) void sgemm_kernel(
    const float* __restrict__ A, const float* __restrict__ B,
    const float* __restrict__ bias, float* __restrict__ C,
    int M, int N, int K, float alpha,
    long strideA, long strideB, long strideC)
{
    __shared__ float As[2][BK][BM];  // A stored K-outer (transposed): stride-1 in M
    __shared__ float Bs[2][BK][BN];

    const int bx = blockIdx.x;          // N tile
    const int by = blockIdx.y;          // M tile
    A += (long)blockIdx.z * strideA;
    B += (long)blockIdx.z * strideB;
    C += (long)blockIdx.z * strideC;

    const int tid = threadIdx.x;
    const int tx = tid & 15;            // 16 thread-cols
    const int ty = tid >> 4;            // 16 thread-rows

    // Global-load mapping (float4):
    // A tile (and B tile in NT mode): 128 rows x 16 cols
    const int ldRow = tid >> 2;         // 0..63 (two passes: +0, +64)
    const int ldCol = (tid & 3) * 4;    // 0,4,8,12
    // B tile in NN mode: 16 rows(k) x 128 cols(n)
    const int nnK = tid >> 5;           // 0..7 (two passes: +0, +8)
    const int nnN = (tid & 31) * 4;     // 0..124

    // ---- prologue: load tile k0=0 straight into buffer 0 ----
    {
        #pragma unroll
        for (int p = 0; p < 2; p++) {
            int r = ldRow + p * 64;
            float4 v = *(const float4*)&A[(long)(by * BM + r) * K + ldCol];
            As[0][ldCol + 0][r] = v.x;
            As[0][ldCol + 1][r] = v.y;
            As[0][ldCol + 2][r] = v.z;
            As[0][ldCol + 3][r] = v.w;
        }
        if (TRANS_B) {
            #pragma unroll
            for (int p = 0; p < 2; p++) {
                int r = ldRow + p * 64;  // n index
                float4 v = *(const float4*)&B[(long)(bx * BN + r) * K + ldCol];
                Bs[0][ldCol + 0][r] = v.x;
                Bs[0][ldCol + 1][r] = v.y;
                Bs[0][ldCol + 2][r] = v.z;
                Bs[0][ldCol + 3][r] = v.w;
            }
        } else {
            #pragma unroll
            for (int p = 0; p < 2; p++) {
                int kk = nnK + p * 8;
                float4 v = *(const float4*)&B[(long)kk * N + bx * BN + nnN];
                *(float4*)&Bs[0][kk][nnN] = v;
            }
        }
    }
    __syncthreads();

    float acc[TM][TN] = {};
    int cur = 0;

    for (int k0 = 0; k0 < K; k0 += BK) {
        const int knext = k0 + BK;
        const bool has_next = knext < K;

        // ---- prefetch next tile into registers ----
        float4 pa0, pa1, pb0, pb1;
        if (has_next) {
            pa0 = *(const float4*)&A[(long)(by * BM + ldRow) * K + knext + ldCol];
            pa1 = *(const float4*)&A[(long)(by * BM + ldRow + 64) * K + knext + ldCol];
            if (TRANS_B) {
                pb0 = *(const float4*)&B[(long)(bx * BN + ldRow) * K + knext + ldCol];
                pb1 = *(const float4*)&B[(long)(bx * BN + ldRow + 64) * K + knext + ldCol];
            } else {
                pb0 = *(const float4*)&B[(long)(knext + nnK) * N + bx * BN + nnN];
                pb1 = *(const float4*)&B[(long)(knext + nnK + 8) * N + bx * BN + nnN];
            }
        }

        // ---- 8x8 register-tile FMAs on buffer `cur` ----
        #pragma unroll
        for (int kk = 0; kk < BK; kk++) {
            float4 a0 = *(const float4*)&As[cur][kk][ty * TM];
            float4 a1 = *(const float4*)&As[cur][kk][ty * TM + 4];
            float4 b0 = *(const float4*)&Bs[cur][kk][tx * TN];
            float4 b1 = *(const float4*)&Bs[cur][kk][tx * TN + 4];
            float rm[TM] = {a0.x, a0.y, a0.z, a0.w, a1.x, a1.y, a1.z, a1.w};
            float rn[TN] = {b0.x, b0.y, b0.z, b0.w, b1.x, b1.y, b1.z, b1.w};
            #pragma unroll
            for (int i = 0; i < TM; i++)
                #pragma unroll
                for (int j = 0; j < TN; j++)
                    acc[i][j] = fmaf(rm[i], rn[j], acc[i][j]);
        }

        if (!has_next) break;

        // ---- commit prefetched tile into the other buffer ----
        const int nxt = cur ^ 1;
        As[nxt][ldCol + 0][ldRow]      = pa0.x;
        As[nxt][ldCol + 1][ldRow]      = pa0.y;
        As[nxt][ldCol + 2][ldRow]      = pa0.z;
        As[nxt][ldCol + 3][ldRow]      = pa0.w;
        As[nxt][ldCol + 0][ldRow + 64] = pa1.x;
        As[nxt][ldCol + 1][ldRow + 64] = pa1.y;
        As[nxt][ldCol + 2][ldRow + 64] = pa1.z;
        As[nxt][ldCol + 3][ldRow + 64] = pa1.w;
        if (TRANS_B) {
            Bs[nxt][ldCol + 0][ldRow]      = pb0.x;
            Bs[nxt][ldCol + 1][ldRow]      = pb0.y;
            Bs[nxt][ldCol + 2][ldRow]      = pb0.z;
            Bs[nxt][ldCol + 3][ldRow]      = pb0.w;
            Bs[nxt][ldCol + 0][ldRow + 64] = pb1.x;
            Bs[nxt][ldCol + 1][ldRow + 64] = pb1.y;
            Bs[nxt][ldCol + 2][ldRow + 64] = pb1.z;
            Bs[nxt][ldCol + 3][ldRow + 64] = pb1.w;
        } else {
            *(float4*)&Bs[nxt][nnK][nnN]     = pb0;
            *(float4*)&Bs[nxt][nnK + 8][nnN] = pb1;
        }
        __syncthreads();
        cur = nxt;
    }

    // ---- epilogue: C = alpha*acc (+ bias) ----
    const int rowC = by * BM + ty * TM;
    const int colC = bx * BN + tx * TN;
    float bb[TN];
    #pragma unroll
    for (int j = 0; j < TN; j++) bb[j] = bias ? bias[colC + j] : 0.0f;

    #pragma unroll
    for (int i = 0; i < TM; i++) {
        float4 o0, o1;
        o0.x = fmaf(alpha, acc[i][0], bb[0]);
        o0.y = fmaf(alpha, acc[i][1], bb[1]);
        o0.z = fmaf(alpha, acc[i][2], bb[2]);
        o0.w = fmaf(alpha, acc[i][3], bb[3]);
        o1.x = fmaf(alpha, acc[i][4], bb[4]);
        o1.y = fmaf(alpha, acc[i][5], bb[5]);
        o1.z = fmaf(alpha, acc[i][6], bb[6]);
        o1.w = fmaf(alpha, acc[i][7], bb[7]);
        *(float4*)&C[(long)(rowC + i) * N + colC] = o0;
        *(float4*)&C[(long)(rowC + i) * N + colC + 4] = o1;
    }
}

// Rowwise softmax over 4096-wide rows. One block (256 threads) per row;
// 16 floats per thread held in registers across the 3 phases.
__global__ __launch_bounds__(256) void softmax_kernel(float* __restrict__ S)
{
    const int COLS = 4096;
    float* row = S + (long)blockIdx.x * COLS;
    const int tid = threadIdx.x;
    float4* row4 = (float4*)row;

    float4 v[4];
    float m = -3.4e38f;
    #pragma unroll
    for (int i = 0; i < 4; i++) {
        v[i] = row4[tid + i * 256];
        m = fmaxf(m, fmaxf(fmaxf(v[i].x, v[i].y), fmaxf(v[i].z, v[i].w)));
    }
    #pragma unroll
    for (int o = 16; o > 0; o >>= 1) m = fmaxf(m, __shfl_xor_sync(0xffffffffu, m, o));
    __shared__ float smax[8];
    if ((tid & 31) == 0) smax[tid >> 5] = m;
    __syncthreads();
    float rmax = smax[0];
    #pragma unroll
    for (int i = 1; i < 8; i++) rmax = fmaxf(rmax, smax[i]);

    float s = 0.0f;
    #pragma unroll
    for (int i = 0; i < 4; i++) {
        v[i].x = __expf(v[i].x - rmax);
        v[i].y = __expf(v[i].y - rmax);
        v[i].z = __expf(v[i].z - rmax);
        v[i].w = __expf(v[i].w - rmax);
        s += v[i].x + v[i].y + v[i].z + v[i].w;
    }
    #pragma unroll
    for (int o = 16; o > 0; o >>= 1) s += __shfl_xor_sync(0xffffffffu, s, o);
    __shared__ float ssum[8];
    if ((tid & 31) == 0) ssum[tid >> 5] = s;
    __syncthreads();
    float tot = 0.0f;
    #pragma unroll
    for (int i = 0; i < 8; i++) tot += ssum[i];
    float inv = 1.0f / tot;

    #pragma unroll
    for (int i = 0; i < 4; i++) {
        v[i].x *= inv; v[i].y *= inv; v[i].z *= inv; v[i].w *= inv;
        row4[tid + i * 256] = v[i];
    }
}

extern "C" void kernel_launch(void* const* d_in, const int* in_sizes, int n_in,
                              void* d_out, int out_size)
{
    const float* X  = (const float*)d_in[0];
    const float* Wq = (const float*)d_in[1];
    const float* Wk = (const float*)d_in[2];
    const float* Wv = (const float*)d_in[3];
    const float* bq = (const float*)d_in[4];
    const float* bk = (const float*)d_in[5];
    const float* bv = (const float*)d_in[6];
    float* O = (float*)d_out;

    float *Q, *Km, *V, *S;
    cudaGetSymbolAddress((void**)&Q,  g_Q);
    cudaGetSymbolAddress((void**)&Km, g_K);
    cudaGetSymbolAddress((void**)&V,  g_V);
    cudaGetSymbolAddress((void**)&S,  g_S);

    const int Bb = 4, Nn = 4096, Dd = 1024;
    const int Mtot = Bb * Nn;  // 16384
    dim3 blk(256);

    // 1) QKV projections (NN): [16384x1024] x [1024x1024] + bias
    dim3 gq(Dd / BN, Mtot / BM, 1);
    sgemm_kernel<0><<<gq, blk>>>(X, Wq, bq, Q,  Mtot, Dd, Dd, 1.0f, 0, 0, 0);
    sgemm_kernel<0><<<gq, blk>>>(X, Wk, bk, Km, Mtot, Dd, Dd, 1.0f, 0, 0, 0);
    sgemm_kernel<0><<<gq, blk>>>(X, Wv, bv, V,  Mtot, Dd, Dd, 1.0f, 0, 0, 0);

    // 2) S = Q · K^T * (1/sqrt(1024)), batched over B (NT)
    dim3 gs(Nn / BN, Nn / BM, Bb);
    sgemm_kernel<1><<<gs, blk>>>(Q, Km, nullptr, S, Nn, Nn, Dd, 0.03125f,
                                 (long)Nn * Dd, (long)Nn * Dd, (long)Nn * Nn);

    // 3) rowwise softmax over 16384 rows of 4096
    softmax_kernel<<<Bb * Nn, 256>>>(S);

    // 4) O = P · V, batched (NN)
    dim3 gp(Dd / BN, Nn / BM, Bb);
    sgemm_kernel<0><<<gp, blk>>>(S, V, nullptr, O, Nn, Dd, Nn, 1.0f,
                                 (long)Nn * Nn, (long)Nn * Dd, (long)Nn * Dd);
}

// round 6
// speedup vs baseline: 2.7259x; 2.7259x over previous
#include <cuda_runtime.h>
#include <cuda_bf16.h>
#include <cstdint>

// SelfAttention B=4, N=4096, d=1024 fp32.
// Round 6 (resubmit of R4/R5 after two broker-infra failures; R1->R2 precedent
// shows identical source passing on retry). Harness compiles via compute_100
// PTX (no 'a' suffix) -> tcgen05 unavailable. Legacy tensor-core path:
// mma.sync.m16n8k16 bf16, fp32 accumulate, bf16 hi/lo 3-MMA split.
// Stages: QKV proj -> S=QK^T/32 -> softmax -> O=P.V, all NT GEMMs (B=[N,K]).

#define BM 128
#define BN 128
#define BK 32
#define STAGES 3
#define THREADS 256

#define TILE_BYTES (128 * 64)            // 128 rows x 32 bf16 (64B)
#define OFF_AH 0
#define OFF_AL TILE_BYTES
#define OFF_BH (2 * TILE_BYTES)
#define OFF_BL (3 * TILE_BYTES)
#define STAGE_BYTES (4 * TILE_BYTES)     // 32 KB
#define GEMM_SMEM (STAGES * STAGE_BYTES) // 96 KB

// ---------------- scratch ----------------
__device__ __nv_bfloat16 g_Xhi[16384l*1024], g_Xlo[16384l*1024];
__device__ __nv_bfloat16 g_Wqt_hi[1024l*1024], g_Wqt_lo[1024l*1024];
__device__ __nv_bfloat16 g_Wkt_hi[1024l*1024], g_Wkt_lo[1024l*1024];
__device__ __nv_bfloat16 g_Wvt_hi[1024l*1024], g_Wvt_lo[1024l*1024];
__device__ __nv_bfloat16 g_Qhi[16384l*1024], g_Qlo[16384l*1024];
__device__ __nv_bfloat16 g_Khi[16384l*1024], g_Klo[16384l*1024];
__device__ float         g_V [16384l*1024];
__device__ __nv_bfloat16 g_Vthi[4l*1024*4096], g_Vtlo[4l*1024*4096];
__device__ float         g_S [4l*4096*4096];
__device__ __nv_bfloat16 g_Phi[16384l*4096], g_Plo[16384l*4096];

// ---------------- helpers ----------------
__device__ __forceinline__ uint32_t smem_u32(const void* p) {
    uint32_t a;
    asm("{ .reg .u64 t; cvta.to.shared.u64 t, %1; cvt.u32.u64 %0, t; }" : "=r"(a) : "l"(p));
    return a;
}
__device__ __forceinline__ void cp16(uint32_t dst, const void* src) {
    asm volatile("cp.async.cg.shared.global [%0], [%1], 16;" :: "r"(dst), "l"(src));
}
#define CP_COMMIT() asm volatile("cp.async.commit_group;" ::: "memory")
#define CP_WAIT1()  asm volatile("cp.async.wait_group 1;" ::: "memory")

__device__ __forceinline__ void ldsm4(uint32_t* r, uint32_t a) {
    asm volatile("ldmatrix.sync.aligned.m8n8.x4.shared.b16 {%0,%1,%2,%3}, [%4];"
                 : "=r"(r[0]), "=r"(r[1]), "=r"(r[2]), "=r"(r[3]) : "r"(a));
}
__device__ __forceinline__ void ldsm2(uint32_t* r, uint32_t a) {
    asm volatile("ldmatrix.sync.aligned.m8n8.x2.shared.b16 {%0,%1}, [%2];"
                 : "=r"(r[0]), "=r"(r[1]) : "r"(a));
}
__device__ __forceinline__ void mma_bf16(float* d, const uint32_t* a, const uint32_t* b) {
    asm volatile(
        "mma.sync.aligned.m16n8k16.row.col.f32.bf16.bf16.f32 "
        "{%0,%1,%2,%3}, {%4,%5,%6,%7}, {%8,%9}, {%0,%1,%2,%3};"
        : "+f"(d[0]), "+f"(d[1]), "+f"(d[2]), "+f"(d[3])
        : "r"(a[0]), "r"(a[1]), "r"(a[2]), "r"(a[3]), "r"(b[0]), "r"(b[1]));
}
__device__ __forceinline__ void split2(float v, __nv_bfloat16& h, __nv_bfloat16& l) {
    h = __float2bfloat16(v);
    l = __float2bfloat16(v - __bfloat162float(h));
}

// ---------------- GEMM: C = alpha*(A·B^T) + bias; A[M,K], B[N,K] hi/lo bf16 ----------------
// SPLIT=1: emit C as hi/lo bf16 pair; SPLIT=0: fp32.
template <int SPLIT>
__global__ __launch_bounds__(THREADS)
void gemm_mma(const __nv_bfloat16* __restrict__ Ahi, const __nv_bfloat16* __restrict__ Alo,
              const __nv_bfloat16* __restrict__ Bhi, const __nv_bfloat16* __restrict__ Blo,
              const float* __restrict__ bias,
              float* __restrict__ Cf,
              __nv_bfloat16* __restrict__ Chi, __nv_bfloat16* __restrict__ Clo,
              int N, int K, float alpha,
              long sA, long sB, long sC)
{
    extern __shared__ __align__(1024) char smem[];
    const uint32_t sb = smem_u32(smem);
    const int tid = threadIdx.x;
    const int lane = tid & 31;
    const int wid = tid >> 5;
    const int warpM = wid & 1;    // 2 warps in M (64 rows each)
    const int warpN = wid >> 1;   // 4 warps in N (32 cols each)
    const int bx = blockIdx.x, by = blockIdx.y, bz = blockIdx.z;

    Ahi += (long)bz * sA;  Alo += (long)bz * sA;
    Bhi += (long)bz * sB;  Blo += (long)bz * sB;

    const long aRow0 = (long)by * BM;
    const long bRow0 = (long)bx * BN;
    const int ktiles = K / BK;

    // cp.async chunk mapping: per tile 512 x 16B chunks; thread does c=tid, tid+256.
    // smem layout per tile: row r (64B) at r*64, 16B seg swizzled: seg^((r>>1)&3).
    auto load_stage = [&](int kt, int s) {
        const long kOff = (long)kt * BK;
        const uint32_t st = sb + s * STAGE_BYTES;
        #pragma unroll
        for (int h = 0; h < 2; h++) {
            const int c = tid + h * 256;
            const int r = c >> 2, seg = c & 3;
            const uint32_t d = (uint32_t)(r * 64 + ((seg ^ ((r >> 1) & 3)) << 4));
            const long ao = (aRow0 + r) * (long)K + kOff + seg * 8;
            const long bo = (bRow0 + r) * (long)K + kOff + seg * 8;
            cp16(st + OFF_AH + d, Ahi + ao);
            cp16(st + OFF_AL + d, Alo + ao);
            cp16(st + OFF_BH + d, Bhi + bo);
            cp16(st + OFF_BL + d, Blo + bo);
        }
    };

    // ldmatrix lane addressing (precomputed swizzle terms; tile offsets land in
    // bits >= the swizzle source bits, so xor terms are per-lane constants)
    const int la = lane & 15;
    const int rowA = warpM * 64 + la;               // + mi*16
    const uint32_t xsA = (uint32_t)((rowA >> 1) & 3);
    const int ksegA = lane >> 4;                    // 0/1: k halves
    const int lb = lane & 15;
    const int nB = warpN * 32 + (lb & 7);           // + ni*8
    const uint32_t xsB = (uint32_t)((nB >> 1) & 3);
    const int ksegB = (lb >> 3) & 1;

    float acc[4][4][4] = {};

    // prologue (ktiles >= 2 for all our shapes)
    load_stage(0, 0); CP_COMMIT();
    load_stage(1, 1); CP_COMMIT();

    for (int kt = 0; kt < ktiles; kt++) {
        CP_WAIT1();
        __syncthreads();
        const int nk = kt + 2;
        if (nk < ktiles) load_stage(nk, nk % STAGES);
        CP_COMMIT();

        const uint32_t st = sb + (kt % STAGES) * STAGE_BYTES;
        #pragma unroll
        for (int ks = 0; ks < 2; ks++) {
            uint32_t ah[4][4], al[4][4], bh[4][2], bl[4][2];
            const uint32_t kA = (uint32_t)((ks * 2 + ksegA) ^ xsA) << 4;
            const uint32_t kB = (uint32_t)((ks * 2 + ksegB) ^ xsB) << 4;
            #pragma unroll
            for (int mi = 0; mi < 4; mi++)
                ldsm4(ah[mi], st + OFF_AH + (uint32_t)((rowA + mi * 16) * 64) + kA);
            #pragma unroll
            for (int ni = 0; ni < 4; ni++)
                ldsm2(bh[ni], st + OFF_BH + (uint32_t)((nB + ni * 8) * 64) + kB);
            #pragma unroll
            for (int mi = 0; mi < 4; mi++)
                #pragma unroll
                for (int ni = 0; ni < 4; ni++)
                    mma_bf16(acc[mi][ni], ah[mi], bh[ni]);

            #pragma unroll
            for (int ni = 0; ni < 4; ni++)
                ldsm2(bl[ni], st + OFF_BL + (uint32_t)((nB + ni * 8) * 64) + kB);
            #pragma unroll
            for (int mi = 0; mi < 4; mi++)
                #pragma unroll
                for (int ni = 0; ni < 4; ni++)
                    mma_bf16(acc[mi][ni], ah[mi], bl[ni]);

            #pragma unroll
            for (int mi = 0; mi < 4; mi++)
                ldsm4(al[mi], st + OFF_AL + (uint32_t)((rowA + mi * 16) * 64) + kA);
            #pragma unroll
            for (int mi = 0; mi < 4; mi++)
                #pragma unroll
                for (int ni = 0; ni < 4; ni++)
                    mma_bf16(acc[mi][ni], al[mi], bh[ni]);
        }
    }

    // ---- epilogue ----
    const int grp = lane >> 2, qp = lane & 3;
    #pragma unroll
    for (int mi = 0; mi < 4; mi++) {
        #pragma unroll
        for (int ni = 0; ni < 4; ni++) {
            const int col = bx * BN + warpN * 32 + ni * 8 + qp * 2;
            const float b0 = bias ? bias[col] : 0.0f;
            const float b1 = bias ? bias[col + 1] : 0.0f;
            #pragma unroll
            for (int g = 0; g < 2; g++) {
                const long row = (long)by * BM + warpM * 64 + mi * 16 + g * 8 + grp;
                const float v0 = acc[mi][ni][g * 2 + 0] * alpha + b0;
                const float v1 = acc[mi][ni][g * 2 + 1] * alpha + b1;
                if (SPLIT) {
                    alignas(4) __nv_bfloat16 h[2], l[2];
                    split2(v0, h[0], l[0]);
                    split2(v1, h[1], l[1]);
                    *(uint32_t*)(Chi + (long)bz * sC + row * N + col) = *(uint32_t*)h;
                    *(uint32_t*)(Clo + (long)bz * sC + row * N + col) = *(uint32_t*)l;
                } else {
                    float2 o = {v0, v1};
                    *(float2*)(Cf + (long)bz * sC + row * N + col) = o;
                }
            }
        }
    }
}

// ---------------- elementwise fp32 -> hi/lo bf16 ----------------
__global__ __launch_bounds__(256) void convert_split(const float* __restrict__ x,
                                                     __nv_bfloat16* __restrict__ hi,
                                                     __nv_bfloat16* __restrict__ lo)
{
    long i = (long)blockIdx.x * 256 + threadIdx.x;
    float4 v = reinterpret_cast<const float4*>(x)[i];
    alignas(8) __nv_bfloat16 h[4], l[4];
    split2(v.x, h[0], l[0]); split2(v.y, h[1], l[1]);
    split2(v.z, h[2], l[2]); split2(v.w, h[3], l[3]);
    reinterpret_cast<uint2*>(hi)[i] = *reinterpret_cast<uint2*>(h);
    reinterpret_cast<uint2*>(lo)[i] = *reinterpret_cast<uint2*>(l);
}

// ---------------- transpose fp32 [R,C] -> hi/lo bf16 [C,R] ----------------
__global__ __launch_bounds__(256) void transpose_split(const float* __restrict__ in,
                                                       __nv_bfloat16* __restrict__ ohi,
                                                       __nv_bfloat16* __restrict__ olo,
                                                       int R, int C, long sIn, long sOut)
{
    __shared__ float t[32][33];
    in  += (long)blockIdx.z * sIn;
    ohi += (long)blockIdx.z * sOut;
    olo += (long)blockIdx.z * sOut;
    const int c0 = blockIdx.x * 32, r0 = blockIdx.y * 32;
    const int tx = threadIdx.x, ty = threadIdx.y;   // 32 x 8
    #pragma unroll
    for (int j = 0; j < 4; j++)
        t[ty + j * 8][tx] = in[(long)(r0 + ty + j * 8) * C + c0 + tx];
    __syncthreads();
    #pragma unroll
    for (int j = 0; j < 4; j++) {
        float v = t[tx][ty + j * 8];
        __nv_bfloat16 h, l; split2(v, h, l);
        long o = (long)(c0 + ty + j * 8) * R + r0 + tx;
        ohi[o] = h; olo[o] = l;
    }
}

// ---------------- softmax: S fp32 row -> P hi/lo bf16 ----------------
__global__ __launch_bounds__(256) void softmax_split(const float* __restrict__ S,
                                                     __nv_bfloat16* __restrict__ Phi,
                                                     __nv_bfloat16* __restrict__ Plo)
{
    const long rowb = (long)blockIdx.x * 4096;
    const float4* row4 = reinterpret_cast<const float4*>(S + rowb);
    const int tid = threadIdx.x;

    float4 v[4];
    float m = -3.4e38f;
    #pragma unroll
    for (int i = 0; i < 4; i++) {
        v[i] = row4[tid + i * 256];
        m = fmaxf(m, fmaxf(fmaxf(v[i].x, v[i].y), fmaxf(v[i].z, v[i].w)));
    }
    #pragma unroll
    for (int o = 16; o > 0; o >>= 1) m = fmaxf(m, __shfl_xor_sync(0xffffffffu, m, o));
    __shared__ float smax[8];
    if ((tid & 31) == 0) smax[tid >> 5] = m;
    __syncthreads();
    float rmax = smax[0];
    #pragma unroll
    for (int i = 1; i < 8; i++) rmax = fmaxf(rmax, smax[i]);

    float s = 0.0f;
    #pragma unroll
    for (int i = 0; i < 4; i++) {
        v[i].x = __expf(v[i].x - rmax); v[i].y = __expf(v[i].y - rmax);
        v[i].z = __expf(v[i].z - rmax); v[i].w = __expf(v[i].w - rmax);
        s += v[i].x + v[i].y + v[i].z + v[i].w;
    }
    #pragma unroll
    for (int o = 16; o > 0; o >>= 1) s += __shfl_xor_sync(0xffffffffu, s, o);
    __shared__ float ssum[8];
    if ((tid & 31) == 0) ssum[tid >> 5] = s;
    __syncthreads();
    float tot = 0.0f;
    #pragma unroll
    for (int i = 0; i < 8; i++) tot += ssum[i];
    const float inv = 1.0f / tot;

    uint2* ph = reinterpret_cast<uint2*>(Phi + rowb);
    uint2* pl = reinterpret_cast<uint2*>(Plo + rowb);
    #pragma unroll
    for (int i = 0; i < 4; i++) {
        alignas(8) __nv_bfloat16 h[4], l[4];
        split2(v[i].x * inv, h[0], l[0]); split2(v[i].y * inv, h[1], l[1]);
        split2(v[i].z * inv, h[2], l[2]); split2(v[i].w * inv, h[3], l[3]);
        ph[tid + i * 256] = *reinterpret_cast<uint2*>(h);
        pl[tid + i * 256] = *reinterpret_cast<uint2*>(l);
    }
}

// ---------------- host ----------------
extern "C" void kernel_launch(void* const* d_in, const int* in_sizes, int n_in,
                              void* d_out, int out_size)
{
    const float* X  = (const float*)d_in[0];
    const float* Wq = (const float*)d_in[1];
    const float* Wk = (const float*)d_in[2];
    const float* Wv = (const float*)d_in[3];
    const float* bq = (const float*)d_in[4];
    const float* bk = (const float*)d_in[5];
    const float* bv = (const float*)d_in[6];
    float* O = (float*)d_out;

    __nv_bfloat16 *Xhi, *Xlo, *Wqh, *Wql, *Wkh, *Wkl, *Wvh, *Wvl;
    __nv_bfloat16 *Qhi, *Qlo, *Khi, *Klo, *Vth, *Vtl, *Phi, *Plo;
    float *Vf, *S;
    cudaGetSymbolAddress((void**)&Xhi, g_Xhi);  cudaGetSymbolAddress((void**)&Xlo, g_Xlo);
    cudaGetSymbolAddress((void**)&Wqh, g_Wqt_hi); cudaGetSymbolAddress((void**)&Wql, g_Wqt_lo);
    cudaGetSymbolAddress((void**)&Wkh, g_Wkt_hi); cudaGetSymbolAddress((void**)&Wkl, g_Wkt_lo);
    cudaGetSymbolAddress((void**)&Wvh, g_Wvt_hi); cudaGetSymbolAddress((void**)&Wvl, g_Wvt_lo);
    cudaGetSymbolAddress((void**)&Qhi, g_Qhi);  cudaGetSymbolAddress((void**)&Qlo, g_Qlo);
    cudaGetSymbolAddress((void**)&Khi, g_Khi);  cudaGetSymbolAddress((void**)&Klo, g_Klo);
    cudaGetSymbolAddress((void**)&Vf, g_V);
    cudaGetSymbolAddress((void**)&Vth, g_Vthi); cudaGetSymbolAddress((void**)&Vtl, g_Vtlo);
    cudaGetSymbolAddress((void**)&S, g_S);
    cudaGetSymbolAddress((void**)&Phi, g_Phi);  cudaGetSymbolAddress((void**)&Plo, g_Plo);

    cudaFuncSetAttribute(gemm_mma<0>, cudaFuncAttributeMaxDynamicSharedMemorySize, GEMM_SMEM);
    cudaFuncSetAttribute(gemm_mma<1>, cudaFuncAttributeMaxDynamicSharedMemorySize, GEMM_SMEM);

    const int Bb = 4, Nn = 4096, Dd = 1024;
    const int Mtot = Bb * Nn;
    const long nQK = (long)Mtot * Dd;

    // X -> hi/lo; W^T -> hi/lo
    convert_split<<<(int)(nQK / 4 / 256), 256>>>(X, Xhi, Xlo);
    dim3 tb(32, 8);
    transpose_split<<<dim3(32, 32, 1), tb>>>(Wq, Wqh, Wql, Dd, Dd, 0, 0);
    transpose_split<<<dim3(32, 32, 1), tb>>>(Wk, Wkh, Wkl, Dd, Dd, 0, 0);
    transpose_split<<<dim3(32, 32, 1), tb>>>(Wv, Wvh, Wvl, Dd, Dd, 0, 0);

    // Stage 1: Q,K (split out), V (fp32 out)
    dim3 g1(Dd / BN, Mtot / BM, 1);
    gemm_mma<1><<<g1, THREADS, GEMM_SMEM>>>(Xhi, Xlo, Wqh, Wql, bq,
        nullptr, Qhi, Qlo, Dd, Dd, 1.0f, 0, 0, 0);
    gemm_mma<1><<<g1, THREADS, GEMM_SMEM>>>(Xhi, Xlo, Wkh, Wkl, bk,
        nullptr, Khi, Klo, Dd, Dd, 1.0f, 0, 0, 0);
    gemm_mma<0><<<g1, THREADS, GEMM_SMEM>>>(Xhi, Xlo, Wvh, Wvl, bv,
        Vf, nullptr, nullptr, Dd, Dd, 1.0f, 0, 0, 0);

    // V^T per batch -> hi/lo [d_new, N]
    transpose_split<<<dim3(32, 128, Bb), tb>>>(Vf, Vth, Vtl, Nn, Dd,
        (long)Nn * Dd, (long)Dd * Nn);

    // Stage 2: S = (Q·K^T)/32
    dim3 g2(Nn / BN, Nn / BM, Bb);
    gemm_mma<0><<<g2, THREADS, GEMM_SMEM>>>(Qhi, Qlo, Khi, Klo, nullptr,
        S, nullptr, nullptr, Nn, Dd, 0.03125f, (long)Nn * Dd, (long)Nn * Dd, (long)Nn * Nn);

    // Stage 3: softmax -> P hi/lo
    softmax_split<<<Mtot, 256>>>(S, Phi, Plo);

    // Stage 4: O = P·V  (B operand = V^T [d_new, N])
    dim3 g4(Dd / BN, Nn / BM, Bb);
    gemm_mma<0><<<g4, THREADS, GEMM_SMEM>>>(Phi, Plo, Vth, Vtl, nullptr,
        O, nullptr, nullptr, Dd, Nn, 1.0f, (long)Nn * Nn, (long)Dd * Nn, (long)Nn * Dd);
}